// round 15
// baseline (speedup 1.0000x reference)
#include <cuda_runtime.h>
#include <math.h>

#define DM 2048
#define NE 8
#define SPR_T 256
#define NT 8          // 32-row tiles per dim (256/32)
#define KSL 8         // k-slices
#define PITCH 40      // smem row pitch: bank-group = (2*row + c') mod 8

// ---- device scratch (no allocations allowed) ----
__device__ float g_bsum[256 * 16];          // per-router-block partials (8 sumprob + 8 count)
__device__ float g_sprpart[144];            // per-simB-block SPR partials
__device__ float g_xnorm[SPR_T * DM];       // 2 MB, L2-resident
__device__ float g_rnorm[SPR_T * NE];
__device__ float g_xsimp[288 * 1024];       // partial gram tiles (36 pairs x 8 slices)

// packed f32x2 FMA (sm_100+; ptxas never auto-fuses, PTX-only)
__device__ __forceinline__ unsigned long long ffma2(
    unsigned long long a, unsigned long long b, unsigned long long c) {
    unsigned long long d;
    asm("fma.rn.f32x2 %0, %1, %2, %3;" : "=l"(d) : "l"(a), "l"(b), "l"(c));
    return d;
}
__device__ __forceinline__ float pk_lo(unsigned long long v) {
    return __uint_as_float((unsigned)v);
}
__device__ __forceinline__ float pk_hi(unsigned long long v) {
    return __uint_as_float((unsigned)(v >> 32));
}

// ---------------------------------------------------------------------------
// Router: 256-thread blocks, split-8 (8 lanes/token), 2 tokens per thread
// (oct, oct+32) so each W LDS.128 feeds 4 packed FMAs. 64 tokens/block,
// grid 256; 3 blocks/SM by smem -> 24 warps resident.
__global__ void __launch_bounds__(256) router_k(
    const float* __restrict__ x, const float* __restrict__ W,
    float* __restrict__ probs, float* __restrict__ idxo, float* __restrict__ tko,
    int n_tok)
{
    extern __shared__ ulonglong2 sW[];               // [NE][512] 16B packs = 64 KB
    const ulonglong2* Wg = (const ulonglong2*)W;
    for (int i = threadIdx.x; i < NE * 512; i += 256) sW[i] = Wg[i];
    __syncthreads();

    int tid = threadIdx.x;
    int q = tid & 7;
    int oct = tid >> 3;                               // 0..31
    int tb = blockIdx.x * 64 + oct;                   // tokens tb, tb+32

    unsigned long long acc0[NE], acc1[NE];
#pragma unroll
    for (int e = 0; e < NE; e++) { acc0[e] = 0ull; acc1[e] = 0ull; }

    const ulonglong2* xr0 = (const ulonglong2*)x + (size_t)tb * 512 + q;
    const ulonglong2* xr1 = xr0 + (size_t)32 * 512;
#pragma unroll 4
    for (int i = 0; i < 64; i++) {
        ulonglong2 xv0 = xr0[i * 8];
        ulonglong2 xv1 = xr1[i * 8];
#pragma unroll
        for (int e = 0; e < NE; e++) {
            ulonglong2 wv = sW[e * 512 + q + i * 8];
            acc0[e] = ffma2(xv0.x, wv.x, acc0[e]);
            acc0[e] = ffma2(xv0.y, wv.y, acc0[e]);
            acc1[e] = ffma2(xv1.x, wv.x, acc1[e]);
            acc1[e] = ffma2(xv1.y, wv.y, acc1[e]);
        }
    }

    float lsum[NE], lcnt[NE];
#pragma unroll
    for (int e = 0; e < NE; e++) { lsum[e] = 0.f; lcnt[e] = 0.f; }

#pragma unroll
    for (int j = 0; j < 2; j++) {
        float a[NE];
#pragma unroll
        for (int e = 0; e < NE; e++) {
            unsigned long long v = j == 0 ? acc0[e] : acc1[e];
            a[e] = pk_lo(v) + pk_hi(v);
        }
#pragma unroll
        for (int e = 0; e < NE; e++) {
#pragma unroll
            for (int o = 1; o < 8; o <<= 1)
                a[e] += __shfl_xor_sync(0xffffffffu, a[e], o);
        }
        if (q == 0) {
            int t = tb + 32 * j;
            float m = a[0];
#pragma unroll
            for (int e = 1; e < NE; e++) m = fmaxf(m, a[e]);
            float p[NE], s = 0.f;
#pragma unroll
            for (int e = 0; e < NE; e++) { p[e] = expf(a[e] - m); s += p[e]; }
            float inv = 1.f / s;
#pragma unroll
            for (int e = 0; e < NE; e++) { p[e] *= inv; lsum[e] += p[e]; }

            float4* po = (float4*)(probs + (size_t)t * NE);
            po[0] = make_float4(p[0], p[1], p[2], p[3]);
            po[1] = make_float4(p[4], p[5], p[6], p[7]);

            // top-2, lowest-index-first tie-break (strict >)
            int i1 = 0; float v1 = p[0];
#pragma unroll
            for (int e = 1; e < NE; e++) if (p[e] > v1) { v1 = p[e]; i1 = e; }
            int i2 = (i1 == 0) ? 1 : 0; float v2 = p[i2];
#pragma unroll
            for (int e = 0; e < NE; e++)
                if (e != i1 && p[e] > v2) { v2 = p[e]; i2 = e; }
            lcnt[i1] += 1.f; lcnt[i2] += 1.f;

            float rn = 1.f / (v1 + v2);
            ((float2*)idxo)[t] = make_float2((float)i1, (float)i2);
            ((float2*)tko)[t]  = make_float2(v1 * rn, v2 * rn);
        }
    }

    // block-level aux reduction -> per-block partial store (no atomics)
    __shared__ float red[8][16];
    float v16[16];
#pragma unroll
    for (int e = 0; e < NE; e++) { v16[e] = lsum[e]; v16[NE + e] = lcnt[e]; }
#pragma unroll
    for (int j = 0; j < 16; j++) {
#pragma unroll
        for (int o = 16; o > 0; o >>= 1)
            v16[j] += __shfl_down_sync(0xffffffffu, v16[j], o);
    }
    if ((tid & 31) == 0) {
#pragma unroll
        for (int j = 0; j < 16; j++) red[tid >> 5][j] = v16[j];
    }
    __syncthreads();
    if (tid < 16) {
        float s = 0.f;
#pragma unroll
        for (int w = 0; w < 8; w++) s += red[w][tid];
        g_bsum[blockIdx.x * 16 + tid] = s;
    }
}

// ---------------------------------------------------------------------------
// One block per sampled token: L2-normalize x row -> g_xnorm, probs row -> g_rnorm.
__global__ void __launch_bounds__(256) spr_gather_k(
    const float* __restrict__ x, const int* __restrict__ spr_idx,
    const float* __restrict__ probs)
{
    int b = blockIdx.x;
    int t = spr_idx[b];
    const float4* xr = (const float4*)(x + (size_t)t * DM);
    float4 a = xr[threadIdx.x];
    float4 bq = xr[threadIdx.x + 256];
    float ss = a.x * a.x + a.y * a.y + a.z * a.z + a.w * a.w
             + bq.x * bq.x + bq.y * bq.y + bq.z * bq.z + bq.w * bq.w;
#pragma unroll
    for (int o = 16; o > 0; o >>= 1) ss += __shfl_down_sync(0xffffffffu, ss, o);
    __shared__ float wred[8];
    __shared__ float s_inv;
    if ((threadIdx.x & 31) == 0) wred[threadIdx.x >> 5] = ss;
    __syncthreads();
    if (threadIdx.x == 0) {
        float tot = 0.f;
#pragma unroll
        for (int w = 0; w < 8; w++) tot += wred[w];
        s_inv = 1.f / fmaxf(sqrtf(tot), 1e-12f);
    }
    __syncthreads();
    float inv = s_inv;
    float4* xo = (float4*)(g_xnorm + (size_t)b * DM);
    xo[threadIdx.x]       = make_float4(a.x * inv, a.y * inv, a.z * inv, a.w * inv);
    xo[threadIdx.x + 256] = make_float4(bq.x * inv, bq.y * inv, bq.z * inv, bq.w * inv);
    if (threadIdx.x == 0) {
        float r[NE], s2 = 0.f;
#pragma unroll
        for (int e = 0; e < NE; e++) {
            r[e] = probs[(size_t)t * NE + e];
            s2 = fmaf(r[e], r[e], s2);
        }
        float ri = 1.f / fmaxf(sqrtf(s2), 1e-12f);
#pragma unroll
        for (int e = 0; e < NE; e++) g_rnorm[b * NE + e] = r[e] * ri;
    }
}

// ---------------------------------------------------------------------------
// Phase A: 32x32 block tiles, 4x4 register tiles, conflict-free swizzle.
// Pitch 40 + swizzle c' = (c + (row>>2)) & 7  => bank-group (2*row + c') mod 8.
__global__ void __launch_bounds__(256) spr_simA_k() {
    __shared__ float sA[4][32][PITCH];
    __shared__ float sB[4][32][PITCH];
    __shared__ float ps[4][1024];

    int pair = blockIdx.x >> 3, ks = blockIdx.x & 7;
    int idx = pair, bi = 0;
    while (idx >= NT - bi) { idx -= NT - bi; bi++; }
    int bj = bi + idx;
    int i0 = bi * 32, j0 = bj * 32;
    int tid = threadIdx.x;

    int g = tid >> 6;                   // k-group 0..3 (64 k each)
    int w = tid & 63;
    int ti = w >> 3, tj = w & 7;        // 8x8 grid, thread owns 4x4 outputs
    int srow = w >> 1, half = w & 1;

    float acc[4][4];
#pragma unroll
    for (int u = 0; u < 4; u++)
#pragma unroll
        for (int v = 0; v < 4; v++) acc[u][v] = 0.f;

#pragma unroll
    for (int cc = 0; cc < 2; cc++) {
        int kb = ks * 256 + g * 64 + cc * 32;
        __syncthreads();
        {
            const float4* pa = (const float4*)&g_xnorm[(size_t)(i0 + srow) * DM + kb + half * 16];
            const float4* pb = (const float4*)&g_xnorm[(size_t)(j0 + srow) * DM + kb + half * 16];
#pragma unroll
            for (int u = 0; u < 4; u++) {
                int cs = ((half * 4 + u) + (srow >> 2)) & 7;
                *(float4*)&sA[g][srow][cs * 4] = pa[u];
                *(float4*)&sB[g][srow][cs * 4] = pb[u];
            }
        }
        __syncthreads();
#pragma unroll
        for (int k4 = 0; k4 < 8; k4++) {
            float4 av[4], bv[4];
#pragma unroll
            for (int u = 0; u < 4; u++)
                av[u] = *(const float4*)&sA[g][4 * ti + u][((k4 + ti) & 7) * 4];
#pragma unroll
            for (int v = 0; v < 4; v++)
                bv[v] = *(const float4*)&sB[g][4 * tj + v][((k4 + tj) & 7) * 4];
#pragma unroll
            for (int u = 0; u < 4; u++)
#pragma unroll
                for (int v = 0; v < 4; v++) {
                    acc[u][v] = fmaf(av[u].x, bv[v].x, acc[u][v]);
                    acc[u][v] = fmaf(av[u].y, bv[v].y, acc[u][v]);
                    acc[u][v] = fmaf(av[u].z, bv[v].z, acc[u][v]);
                    acc[u][v] = fmaf(av[u].w, bv[v].w, acc[u][v]);
                }
        }
    }

#pragma unroll
    for (int u = 0; u < 4; u++)
#pragma unroll
        for (int v = 0; v < 4; v++)
            ps[g][(4 * ti + u) * 32 + 4 * tj + v] = acc[u][v];
    __syncthreads();

    int o0 = tid * 4;
    float4 r;
    r.x = ps[0][o0 + 0] + ps[1][o0 + 0] + ps[2][o0 + 0] + ps[3][o0 + 0];
    r.y = ps[0][o0 + 1] + ps[1][o0 + 1] + ps[2][o0 + 1] + ps[3][o0 + 1];
    r.z = ps[0][o0 + 2] + ps[1][o0 + 2] + ps[2][o0 + 2] + ps[3][o0 + 2];
    r.w = ps[0][o0 + 3] + ps[1][o0 + 3] + ps[2][o0 + 3] + ps[3][o0 + 3];
    *(float4*)&g_xsimp[(size_t)blockIdx.x * 1024 + o0] = r;
}

// ---------------------------------------------------------------------------
// Phase B: 144 blocks (4 per pair), 1 output per thread: combine 8 k-slice
// partials, (rsim - xsim)^2, per-block partial (no atomics).
__global__ void __launch_bounds__(256) spr_simB_k() {
    int pair = blockIdx.x >> 2, sub = blockIdx.x & 3;
    int idx = pair, bi = 0;
    while (idx >= NT - bi) { idx -= NT - bi; bi++; }
    int bj = bi + idx;
    int i0 = bi * 32, j0 = bj * 32;
    int tid = threadIdx.x;
    int o = sub * 256 + tid;
    int i = o >> 5, j = o & 31;

    float xsim = 0.f;
#pragma unroll
    for (int s = 0; s < KSL; s++)
        xsim += g_xsimp[(size_t)(pair * KSL + s) * 1024 + o];
    float rsim = 0.f;
#pragma unroll
    for (int e = 0; e < NE; e++)
        rsim = fmaf(g_rnorm[(i0 + i) * NE + e], g_rnorm[(j0 + j) * NE + e], rsim);
    float d = rsim - xsim;
    float v = d * d * ((bi == bj) ? 1.f : 2.f);
#pragma unroll
    for (int o2 = 16; o2 > 0; o2 >>= 1) v += __shfl_down_sync(0xffffffffu, v, o2);
    __shared__ float wsum[8];
    if ((tid & 31) == 0) wsum[tid >> 5] = v;
    __syncthreads();
    if (tid == 0) {
        float s = 0.f;
#pragma unroll
        for (int q = 0; q < 8; q++) s += wsum[q];
        g_sprpart[blockIdx.x] = s;
    }
}

// ---------------------------------------------------------------------------
// Reduce per-block router partials + SPR partials, emit aux loss.
__global__ void __launch_bounds__(256) finalize_k(
    float* __restrict__ aux_out, int n_tok, int nblk)
{
    __shared__ float sm[16][16];
    __shared__ float vals[16];
    int tid = threadIdx.x;
    int v = tid & 15, part = tid >> 4;
    float s = 0.f;
    for (int b = part; b < nblk; b += 16) s += g_bsum[b * 16 + v];
    sm[part][v] = s;
    __syncthreads();
    if (tid < 16) {
        float tot = 0.f;
#pragma unroll
        for (int p = 0; p < 16; p++) tot += sm[p][tid];
        vals[tid] = tot;
    }
    __syncthreads();
    if (tid == 0) {
        float T = (float)n_tok;
        float lb = 0.f, dpsl = 0.f;
        for (int e = 0; e < NE; e++) {
            float Pi = vals[e] / T;
            float fi = vals[NE + e] / (T * 2.f);
            lb = fmaf(fi, Pi, lb);
            dpsl += 0.125f * (logf(0.125f) - logf(Pi));
        }
        lb *= (float)NE;
        float sprs = 0.f;
        for (int p = 0; p < 144; p++) sprs += g_sprpart[p];
        float spr = sprs / (float)(SPR_T * SPR_T);
        aux_out[0] = 0.01f * (lb + dpsl + 0.1f * spr);
    }
}

// ---------------------------------------------------------------------------
extern "C" void kernel_launch(void* const* d_in, const int* in_sizes, int n_in,
                              void* d_out, int out_size) {
    const float* x   = (const float*)d_in[0];
    const float* W   = (const float*)d_in[1];
    const int*   spr = (const int*)d_in[2];
    int n_tok = in_sizes[0] / DM;      // 16384

    float* out   = (float*)d_out;
    float* probs = out;                              // [n_tok, 8]
    float* idxo  = out + (size_t)n_tok * NE;         // [n_tok, 2] as float
    float* tko   = idxo + (size_t)n_tok * 2;         // [n_tok, 2]
    float* aux   = tko + (size_t)n_tok * 2;          // scalar

    cudaFuncSetAttribute(router_k, cudaFuncAttributeMaxDynamicSharedMemorySize,
                         NE * DM * (int)sizeof(float));

    int nblocks = (n_tok + 63) / 64;                 // 256 blocks, 64 tok each

    router_k<<<nblocks, 256, NE * DM * sizeof(float)>>>(x, W, probs, idxo, tko, n_tok);
    spr_gather_k<<<SPR_T, 256>>>(x, spr, probs);
    spr_simA_k<<<36 * KSL, 256>>>();
    spr_simB_k<<<144, 256>>>();
    finalize_k<<<1, 256>>>(aux, n_tok, nblocks);
}

// round 17
// speedup vs baseline: 1.2891x; 1.2891x over previous
#include <cuda_runtime.h>
#include <math.h>

#define DM 2048
#define NE 8
#define SPR_T 256
#define NT 8          // 32-row tiles per dim (256/32)
#define KSL 8         // k-slices
#define PITCH 40      // smem row pitch: bank-group = (2*row + c') mod 8

// ---- device scratch (no allocations allowed) ----
__device__ float g_bsum[256 * 16];          // per-router-block partials (8 sumprob + 8 count)
__device__ float g_sprpart[144];            // per-simB-block SPR partials
__device__ float g_xnorm[SPR_T * DM];       // 2 MB, L2-resident
__device__ float g_rnorm[SPR_T * NE];
__device__ float g_xsimp[288 * 1024];       // partial gram tiles (36 pairs x 8 slices)
__device__ unsigned int g_ticket;           // simB completion counter (self-resetting)

// packed f32x2 FMA (sm_100+; ptxas never auto-fuses, PTX-only)
__device__ __forceinline__ unsigned long long ffma2(
    unsigned long long a, unsigned long long b, unsigned long long c) {
    unsigned long long d;
    asm("fma.rn.f32x2 %0, %1, %2, %3;" : "=l"(d) : "l"(a), "l"(b), "l"(c));
    return d;
}
__device__ __forceinline__ float pk_lo(unsigned long long v) {
    return __uint_as_float((unsigned)v);
}
__device__ __forceinline__ float pk_hi(unsigned long long v) {
    return __uint_as_float((unsigned)(v >> 32));
}

// ---------------------------------------------------------------------------
// Router: EXACT R9 config (best measured): 512-thread blocks, split-8
// (8 lanes/token), 1 token per thread-octet, grid 256, unroll 8.
// Only delta: __ldcs streaming loads for x (zero-reuse stream).
__global__ void __launch_bounds__(512) router_k(
    const float* __restrict__ x, const float* __restrict__ W,
    float* __restrict__ probs, float* __restrict__ idxo, float* __restrict__ tko,
    int n_tok)
{
    extern __shared__ ulonglong2 sW[];               // [NE][512] 16B packs = 64 KB
    const ulonglong2* Wg = (const ulonglong2*)W;
    for (int i = threadIdx.x; i < NE * 512; i += 512) sW[i] = Wg[i];
    __syncthreads();

    int tid = threadIdx.x;
    int q = tid & 7;
    int t = blockIdx.x * 64 + (tid >> 3);            // exact grid: always valid

    unsigned long long a0[NE];
#pragma unroll
    for (int e = 0; e < NE; e++) a0[e] = 0ull;

    const ulonglong2* xr = (const ulonglong2*)x + (size_t)t * 512 + q;
#pragma unroll 8
    for (int i = 0; i < 64; i++) {
        ulonglong2 xv = __ldcs(&xr[i * 8]);
#pragma unroll
        for (int e = 0; e < NE; e++) {
            ulonglong2 wv = sW[e * 512 + q + i * 8];
            a0[e] = ffma2(xv.x, wv.x, a0[e]);
            a0[e] = ffma2(xv.y, wv.y, a0[e]);
        }
    }

    float acc[NE];
#pragma unroll
    for (int e = 0; e < NE; e++) acc[e] = pk_lo(a0[e]) + pk_hi(a0[e]);
#pragma unroll
    for (int e = 0; e < NE; e++) {
#pragma unroll
        for (int o = 1; o < 8; o <<= 1)
            acc[e] += __shfl_xor_sync(0xffffffffu, acc[e], o);
    }

    float lsum[NE], lcnt[NE];
#pragma unroll
    for (int e = 0; e < NE; e++) { lsum[e] = 0.f; lcnt[e] = 0.f; }

    if (q == 0) {
        float m = acc[0];
#pragma unroll
        for (int e = 1; e < NE; e++) m = fmaxf(m, acc[e]);
        float p[NE], s = 0.f;
#pragma unroll
        for (int e = 0; e < NE; e++) { p[e] = expf(acc[e] - m); s += p[e]; }
        float inv = 1.f / s;
#pragma unroll
        for (int e = 0; e < NE; e++) { p[e] *= inv; lsum[e] = p[e]; }

        float4* po = (float4*)(probs + (size_t)t * NE);
        po[0] = make_float4(p[0], p[1], p[2], p[3]);
        po[1] = make_float4(p[4], p[5], p[6], p[7]);

        // top-2, lowest-index-first tie-break (strict >)
        int i1 = 0; float v1 = p[0];
#pragma unroll
        for (int e = 1; e < NE; e++) if (p[e] > v1) { v1 = p[e]; i1 = e; }
        int i2 = (i1 == 0) ? 1 : 0; float v2 = p[i2];
#pragma unroll
        for (int e = 0; e < NE; e++)
            if (e != i1 && p[e] > v2) { v2 = p[e]; i2 = e; }
        lcnt[i1] = 1.f; lcnt[i2] = 1.f;

        float rn = 1.f / (v1 + v2);
        ((float2*)idxo)[t] = make_float2((float)i1, (float)i2);
        ((float2*)tko)[t]  = make_float2(v1 * rn, v2 * rn);
    }

    // block-level aux reduction -> per-block partial store (no atomics)
    __shared__ float red[16][16];
    float v16[16];
#pragma unroll
    for (int e = 0; e < NE; e++) { v16[e] = lsum[e]; v16[NE + e] = lcnt[e]; }
#pragma unroll
    for (int j = 0; j < 16; j++) {
#pragma unroll
        for (int o = 16; o > 0; o >>= 1)
            v16[j] += __shfl_down_sync(0xffffffffu, v16[j], o);
    }
    if ((tid & 31) == 0) {
#pragma unroll
        for (int j = 0; j < 16; j++) red[tid >> 5][j] = v16[j];
    }
    __syncthreads();
    if (tid < 16) {
        float s = 0.f;
#pragma unroll
        for (int w = 0; w < 16; w++) s += red[w][tid];
        g_bsum[blockIdx.x * 16 + tid] = s;
    }
}

// ---------------------------------------------------------------------------
// One block per sampled token: L2-normalize x row -> g_xnorm, probs row -> g_rnorm.
__global__ void __launch_bounds__(256) spr_gather_k(
    const float* __restrict__ x, const int* __restrict__ spr_idx,
    const float* __restrict__ probs)
{
    int b = blockIdx.x;
    int t = spr_idx[b];
    const float4* xr = (const float4*)(x + (size_t)t * DM);
    float4 a = xr[threadIdx.x];
    float4 bq = xr[threadIdx.x + 256];
    float ss = a.x * a.x + a.y * a.y + a.z * a.z + a.w * a.w
             + bq.x * bq.x + bq.y * bq.y + bq.z * bq.z + bq.w * bq.w;
#pragma unroll
    for (int o = 16; o > 0; o >>= 1) ss += __shfl_down_sync(0xffffffffu, ss, o);
    __shared__ float wred[8];
    __shared__ float s_inv;
    if ((threadIdx.x & 31) == 0) wred[threadIdx.x >> 5] = ss;
    __syncthreads();
    if (threadIdx.x == 0) {
        float tot = 0.f;
#pragma unroll
        for (int w = 0; w < 8; w++) tot += wred[w];
        s_inv = 1.f / fmaxf(sqrtf(tot), 1e-12f);
    }
    __syncthreads();
    float inv = s_inv;
    float4* xo = (float4*)(g_xnorm + (size_t)b * DM);
    xo[threadIdx.x]       = make_float4(a.x * inv, a.y * inv, a.z * inv, a.w * inv);
    xo[threadIdx.x + 256] = make_float4(bq.x * inv, bq.y * inv, bq.z * inv, bq.w * inv);
    if (threadIdx.x == 0) {
        float r[NE], s2 = 0.f;
#pragma unroll
        for (int e = 0; e < NE; e++) {
            r[e] = probs[(size_t)t * NE + e];
            s2 = fmaf(r[e], r[e], s2);
        }
        float ri = 1.f / fmaxf(sqrtf(s2), 1e-12f);
#pragma unroll
        for (int e = 0; e < NE; e++) g_rnorm[b * NE + e] = r[e] * ri;
    }
}

// ---------------------------------------------------------------------------
// Phase A: 32x32 block tiles, 4x4 register tiles, conflict-free swizzle.
// Pitch 40 + swizzle c' = (c + (row>>2)) & 7  => bank-group (2*row + c') mod 8.
__global__ void __launch_bounds__(256) spr_simA_k() {
    __shared__ float sA[4][32][PITCH];
    __shared__ float sB[4][32][PITCH];
    __shared__ float ps[4][1024];

    int pair = blockIdx.x >> 3, ks = blockIdx.x & 7;
    int idx = pair, bi = 0;
    while (idx >= NT - bi) { idx -= NT - bi; bi++; }
    int bj = bi + idx;
    int i0 = bi * 32, j0 = bj * 32;
    int tid = threadIdx.x;

    int g = tid >> 6;                   // k-group 0..3 (64 k each)
    int w = tid & 63;
    int ti = w >> 3, tj = w & 7;        // 8x8 grid, thread owns 4x4 outputs
    int srow = w >> 1, half = w & 1;

    float acc[4][4];
#pragma unroll
    for (int u = 0; u < 4; u++)
#pragma unroll
        for (int v = 0; v < 4; v++) acc[u][v] = 0.f;

#pragma unroll
    for (int cc = 0; cc < 2; cc++) {
        int kb = ks * 256 + g * 64 + cc * 32;
        __syncthreads();
        {
            const float4* pa = (const float4*)&g_xnorm[(size_t)(i0 + srow) * DM + kb + half * 16];
            const float4* pb = (const float4*)&g_xnorm[(size_t)(j0 + srow) * DM + kb + half * 16];
#pragma unroll
            for (int u = 0; u < 4; u++) {
                int cs = ((half * 4 + u) + (srow >> 2)) & 7;
                *(float4*)&sA[g][srow][cs * 4] = pa[u];
                *(float4*)&sB[g][srow][cs * 4] = pb[u];
            }
        }
        __syncthreads();
#pragma unroll
        for (int k4 = 0; k4 < 8; k4++) {
            float4 av[4], bv[4];
#pragma unroll
            for (int u = 0; u < 4; u++)
                av[u] = *(const float4*)&sA[g][4 * ti + u][((k4 + ti) & 7) * 4];
#pragma unroll
            for (int v = 0; v < 4; v++)
                bv[v] = *(const float4*)&sB[g][4 * tj + v][((k4 + tj) & 7) * 4];
#pragma unroll
            for (int u = 0; u < 4; u++)
#pragma unroll
                for (int v = 0; v < 4; v++) {
                    acc[u][v] = fmaf(av[u].x, bv[v].x, acc[u][v]);
                    acc[u][v] = fmaf(av[u].y, bv[v].y, acc[u][v]);
                    acc[u][v] = fmaf(av[u].z, bv[v].z, acc[u][v]);
                    acc[u][v] = fmaf(av[u].w, bv[v].w, acc[u][v]);
                }
        }
    }

#pragma unroll
    for (int u = 0; u < 4; u++)
#pragma unroll
        for (int v = 0; v < 4; v++)
            ps[g][(4 * ti + u) * 32 + 4 * tj + v] = acc[u][v];
    __syncthreads();

    int o0 = tid * 4;
    float4 r;
    r.x = ps[0][o0 + 0] + ps[1][o0 + 0] + ps[2][o0 + 0] + ps[3][o0 + 0];
    r.y = ps[0][o0 + 1] + ps[1][o0 + 1] + ps[2][o0 + 1] + ps[3][o0 + 1];
    r.z = ps[0][o0 + 2] + ps[1][o0 + 2] + ps[2][o0 + 2] + ps[3][o0 + 2];
    r.w = ps[0][o0 + 3] + ps[1][o0 + 3] + ps[2][o0 + 3] + ps[3][o0 + 3];
    *(float4*)&g_xsimp[(size_t)blockIdx.x * 1024 + o0] = r;
}

// ---------------------------------------------------------------------------
// Phase B + finalize fused: 144 blocks combine k-slice partials and compute
// (rsim - xsim)^2; the LAST block to finish (ticket) reduces everything and
// writes the aux scalar. Counter self-resets to 0 -> graph-replay safe.
__global__ void __launch_bounds__(256) spr_simB_k(
    float* __restrict__ aux_out, int n_tok, int nblk)
{
    int pair = blockIdx.x >> 2, sub = blockIdx.x & 3;
    int idx = pair, bi = 0;
    while (idx >= NT - bi) { idx -= NT - bi; bi++; }
    int bj = bi + idx;
    int i0 = bi * 32, j0 = bj * 32;
    int tid = threadIdx.x;
    int o = sub * 256 + tid;
    int i = o >> 5, j = o & 31;

    float xsim = 0.f;
#pragma unroll
    for (int s = 0; s < KSL; s++)
        xsim += g_xsimp[(size_t)(pair * KSL + s) * 1024 + o];
    float rsim = 0.f;
#pragma unroll
    for (int e = 0; e < NE; e++)
        rsim = fmaf(g_rnorm[(i0 + i) * NE + e], g_rnorm[(j0 + j) * NE + e], rsim);
    float d = rsim - xsim;
    float v = d * d * ((bi == bj) ? 1.f : 2.f);
#pragma unroll
    for (int o2 = 16; o2 > 0; o2 >>= 1) v += __shfl_down_sync(0xffffffffu, v, o2);
    __shared__ float wsum[8];
    if ((tid & 31) == 0) wsum[tid >> 5] = v;
    __syncthreads();

    __shared__ unsigned int s_last;
    if (tid == 0) {
        float s = 0.f;
#pragma unroll
        for (int q = 0; q < 8; q++) s += wsum[q];
        g_sprpart[blockIdx.x] = s;
        __threadfence();
        unsigned int tk = atomicAdd(&g_ticket, 1u);
        s_last = (tk == 143u) ? 1u : 0u;
        if (s_last) g_ticket = 0u;      // reset for next graph replay
    }
    __syncthreads();

    if (s_last) {
        // final reduction (only in the last-finishing block)
        __shared__ float sm[16][16];
        __shared__ float vals[16];
        int vv = tid & 15, part = tid >> 4;
        float s = 0.f;
        for (int b = part; b < nblk; b += 16) s += g_bsum[b * 16 + vv];
        sm[part][vv] = s;
        __syncthreads();
        if (tid < 16) {
            float tot = 0.f;
#pragma unroll
            for (int p = 0; p < 16; p++) tot += sm[p][tid];
            vals[tid] = tot;
        }
        __syncthreads();
        if (tid == 0) {
            float T = (float)n_tok;
            float lb = 0.f, dpsl = 0.f;
            for (int e = 0; e < NE; e++) {
                float Pi = vals[e] / T;
                float fi = vals[NE + e] / (T * 2.f);
                lb = fmaf(fi, Pi, lb);
                dpsl += 0.125f * (logf(0.125f) - logf(Pi));
            }
            lb *= (float)NE;
            float sprs = 0.f;
            for (int p = 0; p < 144; p++) sprs += g_sprpart[p];
            float spr = sprs / (float)(SPR_T * SPR_T);
            aux_out[0] = 0.01f * (lb + dpsl + 0.1f * spr);
        }
    }
}

// ---------------------------------------------------------------------------
extern "C" void kernel_launch(void* const* d_in, const int* in_sizes, int n_in,
                              void* d_out, int out_size) {
    const float* x   = (const float*)d_in[0];
    const float* W   = (const float*)d_in[1];
    const int*   spr = (const int*)d_in[2];
    int n_tok = in_sizes[0] / DM;      // 16384

    float* out   = (float*)d_out;
    float* probs = out;                              // [n_tok, 8]
    float* idxo  = out + (size_t)n_tok * NE;         // [n_tok, 2] as float
    float* tko   = idxo + (size_t)n_tok * 2;         // [n_tok, 2]
    float* aux   = tko + (size_t)n_tok * 2;          // scalar

    cudaFuncSetAttribute(router_k, cudaFuncAttributeMaxDynamicSharedMemorySize,
                         NE * DM * (int)sizeof(float));

    int nblocks = (n_tok + 63) / 64;                 // 256 blocks, 64 tok each

    router_k<<<nblocks, 512, NE * DM * sizeof(float)>>>(x, W, probs, idxo, tko, n_tok);
    spr_gather_k<<<SPR_T, 256>>>(x, spr, probs);
    spr_simA_k<<<36 * KSL, 256>>>();
    spr_simB_k<<<144, 256>>>(aux, n_tok, nblocks);
}